// round 2
// baseline (speedup 1.0000x reference)
#include <cuda_runtime.h>
#include <math.h>

#define D        128
#define NCOLS    256
#define BM       64
#define BN       128
#define BK       32
#define MAX_NODES 100000

// Scratch: P[n, 0:128] = A[n] (x[n] . W1[j, 0:128]),
//          P[n, 128:256] = B[n] (x[n] . W1[j, 128:256])
__device__ float g_P[(size_t)MAX_NODES * NCOLS];
__device__ int   g_idx_is64;

// ---------------------------------------------------------------------------
// Kernel 0: detect edge_index dtype (int32 vs int64).
// For little-endian int64 indices < 2^31, every odd 32-bit word is 0.
// For int32 indices ~U[0,1e5), odd words are ~never all 0 (p ~ 1e-40).
// ---------------------------------------------------------------------------
__global__ void detect_idx_kernel(const int* __restrict__ ei_words)
{
    int acc = 0;
    #pragma unroll
    for (int i = 1; i < 16; i += 2) acc |= ei_words[i];
    g_idx_is64 = (acc == 0) ? 1 : 0;
}

// ---------------------------------------------------------------------------
// Kernel 1: P = x @ [W1[:, :128] | W1[:, 128:]]^T   (fp32 tiled GEMM)
// grid = (ceil(N/BM), 2), block = 256. Per-thread 8x4 micro-tile.
// ---------------------------------------------------------------------------
__global__ __launch_bounds__(256) void precompute_kernel(
    const float* __restrict__ x,
    const float* __restrict__ W1,
    int N)
{
    __shared__ float sA[BK][BM];   // [k][m]  8 KB
    __shared__ float sB[BK][BN];   // [k][n] 16 KB

    const int m0   = blockIdx.x * BM;
    const int half = blockIdx.y;            // 0 -> A cols, 1 -> B cols
    const int tid  = threadIdx.x;
    const int tm   = (tid >> 5) * 8;        // 8 m-rows per thread
    const int tn   = (tid & 31) * 4;        // 4 n-cols per thread

    float acc[8][4];
    #pragma unroll
    for (int i = 0; i < 8; i++)
        #pragma unroll
        for (int j = 0; j < 4; j++) acc[i][j] = 0.f;

    for (int kb = 0; kb < D; kb += BK) {
        #pragma unroll
        for (int i = tid; i < BM * (BK / 4); i += 256) {
            int r  = i / (BK / 4);
            int c4 = (i % (BK / 4)) * 4;
            int m  = m0 + r;
            float4 v = make_float4(0.f, 0.f, 0.f, 0.f);
            if (m < N)
                v = *reinterpret_cast<const float4*>(&x[(size_t)m * D + kb + c4]);
            sA[c4 + 0][r] = v.x;
            sA[c4 + 1][r] = v.y;
            sA[c4 + 2][r] = v.z;
            sA[c4 + 3][r] = v.w;
        }
        #pragma unroll
        for (int i = tid; i < BN * (BK / 4); i += 256) {
            int n  = i / (BK / 4);
            int c4 = (i % (BK / 4)) * 4;
            float4 v = *reinterpret_cast<const float4*>(
                &W1[(size_t)n * NCOLS + half * D + kb + c4]);
            sB[c4 + 0][n] = v.x;
            sB[c4 + 1][n] = v.y;
            sB[c4 + 2][n] = v.z;
            sB[c4 + 3][n] = v.w;
        }
        __syncthreads();

        #pragma unroll 8
        for (int k = 0; k < BK; k++) {
            float4 a0 = *reinterpret_cast<float4*>(&sA[k][tm]);
            float4 a1 = *reinterpret_cast<float4*>(&sA[k][tm + 4]);
            float4 bv = *reinterpret_cast<float4*>(&sB[k][tn]);
            float a[8] = {a0.x, a0.y, a0.z, a0.w, a1.x, a1.y, a1.z, a1.w};
            float b[4] = {bv.x, bv.y, bv.z, bv.w};
            #pragma unroll
            for (int i = 0; i < 8; i++)
                #pragma unroll
                for (int j = 0; j < 4; j++)
                    acc[i][j] = fmaf(a[i], b[j], acc[i][j]);
        }
        __syncthreads();
    }

    #pragma unroll
    for (int i = 0; i < 8; i++) {
        int m = m0 + tm + i;
        if (m < N) {
            float4 v = make_float4(acc[i][0], acc[i][1], acc[i][2], acc[i][3]);
            *reinterpret_cast<float4*>(&g_P[(size_t)m * NCOLS + half * D + tn]) = v;
        }
    }
}

// ---------------------------------------------------------------------------
// Kernel 2: per-edge MLP tail. One warp per edge.
//   s = sum_j relu(A[src][j] + B[dst][j] + b1[j]) * w2[j]
//   out[e] = sigmoid(relu(s + b2))
// ---------------------------------------------------------------------------
__global__ __launch_bounds__(256) void edge_kernel(
    const void* __restrict__ edge_index,
    const float* __restrict__ b1,
    const float* __restrict__ W2,
    const float* __restrict__ b2,
    float* __restrict__ out,
    int E)
{
    const int lane   = threadIdx.x & 31;
    const int warp   = (blockIdx.x * blockDim.x + threadIdx.x) >> 5;
    const int nwarps = (gridDim.x * blockDim.x) >> 5;

    const int is64 = g_idx_is64;
    const int*       ei32 = (const int*)edge_index;
    const long long* ei64 = (const long long*)edge_index;

    const float4* __restrict__ P4 = reinterpret_cast<const float4*>(g_P);
    const float4 bias = reinterpret_cast<const float4*>(b1)[lane];
    const float4 w2   = reinterpret_cast<const float4*>(W2)[lane];
    const float  b2v  = *b2;

    for (int e = warp; e < E; e += nwarps) {
        int s, t;
        if (is64) {
            s = (int)ei64[e];
            t = (int)ei64[E + e];
        } else {
            s = ei32[e];
            t = ei32[E + e];
        }
        float4 a = P4[(size_t)s * 64 + lane];        // A[src], cols 0..127
        float4 b = P4[(size_t)t * 64 + 32 + lane];   // B[dst], cols 128..255

        float v = fmaxf(a.x + b.x + bias.x, 0.f) * w2.x
                + fmaxf(a.y + b.y + bias.y, 0.f) * w2.y
                + fmaxf(a.z + b.z + bias.z, 0.f) * w2.z
                + fmaxf(a.w + b.w + bias.w, 0.f) * w2.w;

        #pragma unroll
        for (int o = 16; o > 0; o >>= 1)
            v += __shfl_xor_sync(0xFFFFFFFFu, v, o);

        if (lane == 0) {
            float h = fmaxf(v + b2v, 0.f);
            out[e] = 1.0f / (1.0f + expf(-h));
        }
    }
}

// ---------------------------------------------------------------------------
// Launch
// Inputs: x[f32 N*128], edge_index[2*E, int32 or int64], W1[f32 128*256],
//         b1[f32 128], W2[f32 128], b2[f32 1]. Output: f32 E.
// ---------------------------------------------------------------------------
extern "C" void kernel_launch(void* const* d_in, const int* in_sizes, int n_in,
                              void* d_out, int out_size)
{
    const float* x  = (const float*)d_in[0];
    const void*  ei = d_in[1];
    const float* W1 = (const float*)d_in[2];
    const float* b1 = (const float*)d_in[3];
    const float* W2 = (const float*)d_in[4];
    const float* b2 = (const float*)d_in[5];
    float*       out = (float*)d_out;

    const int N = in_sizes[0] / D;   // 100000
    const int E = in_sizes[1] / 2;   // 625000

    detect_idx_kernel<<<1, 1>>>((const int*)ei);

    dim3 g1((N + BM - 1) / BM, 2);
    precompute_kernel<<<g1, 256>>>(x, W1, N);

    edge_kernel<<<592, 256>>>(ei, b1, W2, b2, out, E);
}

// round 3
// speedup vs baseline: 1.0133x; 1.0133x over previous
#include <cuda_runtime.h>
#include <math.h>

#define D        128
#define NCOLS    256
#define BM       64
#define BN       128
#define BK       32
#define MAX_NODES 100000

typedef unsigned long long ull;

// Scratch: P[n, 0:128] = A[n] = x[n] . W1[:, 0:128]
//          P[n, 128:256] = B[n] = x[n] . W1[:, 128:256]
__device__ float g_P[(size_t)MAX_NODES * NCOLS];

// ---- packed f32x2 helpers (sm_100+; ptxas never auto-fuses these) ----------
__device__ __forceinline__ ull ffma2(ull a, ull b, ull c) {
    ull d;
    asm("fma.rn.f32x2 %0, %1, %2, %3;" : "=l"(d) : "l"(a), "l"(b), "l"(c));
    return d;
}
__device__ __forceinline__ ull dup2(float v) {
    ull r;
    asm("mov.b64 %0, {%1, %1};" : "=l"(r) : "f"(v));
    return r;
}
__device__ __forceinline__ void unpack2(float& lo, float& hi, ull v) {
    asm("mov.b64 {%0, %1}, %2;" : "=f"(lo), "=f"(hi) : "l"(v));
}

// ---------------------------------------------------------------------------
// Kernel 1: P = x @ [W1[:, :128] | W1[:, 128:]]^T   (fp32 GEMM, f32x2 FMA)
// grid = (ceil(N/BM), 2), block = 256. Per-thread 8m x 4n micro-tile,
// accumulators packed as (m, m+1) pairs -> A operand is a direct 64-bit
// shared load, only B needs a lane-dup.
// ---------------------------------------------------------------------------
__global__ __launch_bounds__(256) void precompute_kernel(
    const float* __restrict__ x,
    const float* __restrict__ W1,
    int N)
{
    __shared__ float sA[BK][BM];   // [k][m]  8 KB
    __shared__ float sB[BK][BN];   // [k][n] 16 KB

    const int m0   = blockIdx.x * BM;
    const int half = blockIdx.y;            // 0 -> A cols, 1 -> B cols
    const int tid  = threadIdx.x;
    const int tm   = (tid >> 5) * 8;        // 8 m-rows per thread (pairs)
    const int tn   = (tid & 31) * 4;        // 4 n-cols per thread

    ull acc[4][4];                           // [(m-pair)][n] packed f32x2
    #pragma unroll
    for (int i = 0; i < 4; i++)
        #pragma unroll
        for (int j = 0; j < 4; j++) acc[i][j] = 0ull;

    for (int kb = 0; kb < D; kb += BK) {
        #pragma unroll
        for (int i = tid; i < BM * (BK / 4); i += 256) {
            int r  = i / (BK / 4);
            int c4 = (i % (BK / 4)) * 4;
            int m  = m0 + r;
            float4 v = make_float4(0.f, 0.f, 0.f, 0.f);
            if (m < N)
                v = *reinterpret_cast<const float4*>(&x[(size_t)m * D + kb + c4]);
            sA[c4 + 0][r] = v.x;
            sA[c4 + 1][r] = v.y;
            sA[c4 + 2][r] = v.z;
            sA[c4 + 3][r] = v.w;
        }
        #pragma unroll
        for (int i = tid; i < BN * (BK / 4); i += 256) {
            int n  = i / (BK / 4);
            int c4 = (i % (BK / 4)) * 4;
            float4 v = *reinterpret_cast<const float4*>(
                &W1[(size_t)n * NCOLS + half * D + kb + c4]);
            sB[c4 + 0][n] = v.x;
            sB[c4 + 1][n] = v.y;
            sB[c4 + 2][n] = v.z;
            sB[c4 + 3][n] = v.w;
        }
        __syncthreads();

        #pragma unroll 8
        for (int k = 0; k < BK; k++) {
            // A pairs straight from shared: (m0,m1)(m2,m3)(m4,m5)(m6,m7)
            ulonglong2 A0 = *reinterpret_cast<const ulonglong2*>(&sA[k][tm]);
            ulonglong2 A1 = *reinterpret_cast<const ulonglong2*>(&sA[k][tm + 4]);
            float4 bv = *reinterpret_cast<const float4*>(&sB[k][tn]);
            ull ap[4] = {A0.x, A0.y, A1.x, A1.y};
            ull bd[4] = {dup2(bv.x), dup2(bv.y), dup2(bv.z), dup2(bv.w)};
            #pragma unroll
            for (int i = 0; i < 4; i++)
                #pragma unroll
                for (int j = 0; j < 4; j++)
                    acc[i][j] = ffma2(ap[i], bd[j], acc[i][j]);
        }
        __syncthreads();
    }

    #pragma unroll
    for (int i = 0; i < 4; i++) {
        float lo0, hi0, lo1, hi1, lo2, hi2, lo3, hi3;
        unpack2(lo0, hi0, acc[i][0]);
        unpack2(lo1, hi1, acc[i][1]);
        unpack2(lo2, hi2, acc[i][2]);
        unpack2(lo3, hi3, acc[i][3]);
        int mlo = m0 + tm + 2 * i;
        if (mlo < N)
            *reinterpret_cast<float4*>(&g_P[(size_t)mlo * NCOLS + half * D + tn]) =
                make_float4(lo0, lo1, lo2, lo3);
        if (mlo + 1 < N)
            *reinterpret_cast<float4*>(&g_P[(size_t)(mlo + 1) * NCOLS + half * D + tn]) =
                make_float4(hi0, hi1, hi2, hi3);
    }
}

// ---------------------------------------------------------------------------
// Kernel 2: per-edge MLP tail. One warp per edge.
//   s = sum_j relu(A[src][j] + B[dst][j] + b1[j]) * w2[j]
//   out[e] = sigmoid(relu(s + b2))
// Dtype of edge_index (int32 vs int64) detected inline: little-endian int64
// indices < 2^31 have every odd 32-bit word zero.
// ---------------------------------------------------------------------------
__global__ __launch_bounds__(256) void edge_kernel(
    const void* __restrict__ edge_index,
    const float* __restrict__ b1,
    const float* __restrict__ W2,
    const float* __restrict__ b2,
    float* __restrict__ out,
    int E)
{
    const int lane   = threadIdx.x & 31;
    const int warp   = (blockIdx.x * blockDim.x + threadIdx.x) >> 5;
    const int nwarps = (gridDim.x * blockDim.x) >> 5;

    const int* ei32 = (const int*)edge_index;
    int det = 0;
    #pragma unroll
    for (int i = 1; i < 16; i += 2) det |= __ldg(&ei32[i]);
    const bool is64 = (det == 0);
    const long long* ei64 = (const long long*)edge_index;

    const float4* __restrict__ P4 = reinterpret_cast<const float4*>(g_P);
    const float4 bias = reinterpret_cast<const float4*>(b1)[lane];
    const float4 w2   = reinterpret_cast<const float4*>(W2)[lane];
    const float  b2v  = *b2;

    for (int e = warp; e < E; e += nwarps) {
        int s, t;
        if (is64) {
            s = (int)ei64[e];
            t = (int)ei64[E + e];
        } else {
            s = ei32[e];
            t = ei32[E + e];
        }
        float4 a = P4[(size_t)s * 64 + lane];        // A[src], cols 0..127
        float4 b = P4[(size_t)t * 64 + 32 + lane];   // B[dst], cols 128..255

        float v = fmaxf(a.x + b.x + bias.x, 0.f) * w2.x
                + fmaxf(a.y + b.y + bias.y, 0.f) * w2.y
                + fmaxf(a.z + b.z + bias.z, 0.f) * w2.z
                + fmaxf(a.w + b.w + bias.w, 0.f) * w2.w;

        #pragma unroll
        for (int o = 16; o > 0; o >>= 1)
            v += __shfl_xor_sync(0xFFFFFFFFu, v, o);

        if (lane == 0) {
            float h = fmaxf(v + b2v, 0.f);
            out[e] = 1.0f / (1.0f + expf(-h));
        }
    }
}

// ---------------------------------------------------------------------------
// Launch
// Inputs: x[f32 N*128], edge_index[2*E i32/i64], W1[f32 128*256], b1[f32 128],
//         W2[f32 128], b2[f32 1]. Output: f32 E.
// ---------------------------------------------------------------------------
extern "C" void kernel_launch(void* const* d_in, const int* in_sizes, int n_in,
                              void* d_out, int out_size)
{
    const float* x  = (const float*)d_in[0];
    const void*  ei = d_in[1];
    const float* W1 = (const float*)d_in[2];
    const float* b1 = (const float*)d_in[3];
    const float* W2 = (const float*)d_in[4];
    const float* b2 = (const float*)d_in[5];
    float*       out = (float*)d_out;

    const int N = in_sizes[0] / D;   // 100000
    const int E = in_sizes[1] / 2;   // 625000

    dim3 g1((N + BM - 1) / BM, 2);
    precompute_kernel<<<g1, 256>>>(x, W1, N);

    edge_kernel<<<592, 256>>>(ei, b1, W2, b2, out, E);
}

// round 5
// speedup vs baseline: 1.1406x; 1.1256x over previous
#include <cuda_runtime.h>
#include <cuda_bf16.h>
#include <math.h>

#define D         128
#define NCOLS     256
#define BM        128
#define SA        136          // smem tile row stride in bf16 elems (272 B)
#define MAX_NODES 100000

typedef unsigned int u32;

__device__ float g_P[(size_t)MAX_NODES * NCOLS];

// ============================================================================
// helpers
// ============================================================================
__device__ __forceinline__ u32 smem_u32(const void* p) {
    u32 a;
    asm("{ .reg .u64 t; cvta.to.shared.u64 t, %1; cvt.u32.u64 %0, t; }"
        : "=r"(a) : "l"(p));
    return a;
}

#define LDMATRIX_X4(r0, r1, r2, r3, addr)                                   \
    asm volatile("ldmatrix.sync.aligned.m8n8.x4.shared.b16 "                \
                 "{%0, %1, %2, %3}, [%4];"                                  \
                 : "=r"(r0), "=r"(r1), "=r"(r2), "=r"(r3) : "r"(addr))

#define LDMATRIX_X2(r0, r1, addr)                                           \
    asm volatile("ldmatrix.sync.aligned.m8n8.x2.shared.b16 "                \
                 "{%0, %1}, [%2];"                                          \
                 : "=r"(r0), "=r"(r1) : "r"(addr))

__device__ __forceinline__ void mma_bf16(float* d, const u32* a, const u32* b) {
    asm volatile(
        "mma.sync.aligned.m16n8k16.row.col.f32.bf16.bf16.f32 "
        "{%0, %1, %2, %3}, {%4, %5, %6, %7}, {%8, %9}, {%0, %1, %2, %3};"
        : "+f"(d[0]), "+f"(d[1]), "+f"(d[2]), "+f"(d[3])
        : "r"(a[0]), "r"(a[1]), "r"(a[2]), "r"(a[3]), "r"(b[0]), "r"(b[1]));
}

// split fp32 pair -> bf16x2 hi word + bf16x2 residual-lo word (low half = f0)
__device__ __forceinline__ void split2(float f0, float f1, u32& h, u32& l) {
    __nv_bfloat16 h0 = __float2bfloat16(f0);
    __nv_bfloat16 h1 = __float2bfloat16(f1);
    float r0 = f0 - __bfloat162float(h0);
    float r1 = f1 - __bfloat162float(h1);
    union { __nv_bfloat162 v; u32 u; } a, b;
    a.v = __nv_bfloat162(h0, h1);
    b.v = __nv_bfloat162(__float2bfloat16(r0), __float2bfloat16(r1));
    h = a.u; l = b.u;
}

// ============================================================================
// Kernel 1: P[:, half*128 : half*128+128] = x @ W1[:, half*128 : +128]^T
// bf16 split-precision mma.sync (3 chains), fp32 accumulate.
// grid = (ceil(N/128), 2), block = 256 (8 warps, 4x2 layout, 32x64 per warp).
// ============================================================================
__global__ __launch_bounds__(256) void precompute_kernel(
    const float* __restrict__ x,
    const float* __restrict__ W1,
    int nN)
{
    extern __shared__ __align__(16) __nv_bfloat16 smem_bf[];
    __nv_bfloat16* aHi = smem_bf;                 // 128 x SA
    __nv_bfloat16* aLo = aHi + 128 * SA;
    __nv_bfloat16* bHi = aLo + 128 * SA;
    __nv_bfloat16* bLo = bHi + 128 * SA;

    const int tid  = threadIdx.x;
    const int wid  = tid >> 5;
    const int lane = tid & 31;
    const int m0   = blockIdx.x * BM;
    const int half = blockIdx.y;

    // ---- convert A tile: x[m0..m0+127, 0:128] fp32 -> bf16 hi/lo ----
    for (int c = tid; c < 128 * 32; c += 256) {
        int r = c >> 5, q = c & 31;               // q = float4 index (k0 = q*4)
        int m = m0 + r;
        float4 v = make_float4(0.f, 0.f, 0.f, 0.f);
        if (m < nN)
            v = *reinterpret_cast<const float4*>(x + (size_t)m * D + q * 4);
        u32 h0, l0, h1, l1;
        split2(v.x, v.y, h0, l0);
        split2(v.z, v.w, h1, l1);
        u32* dh = reinterpret_cast<u32*>(aHi + r * SA + q * 4);
        u32* dl = reinterpret_cast<u32*>(aLo + r * SA + q * 4);
        dh[0] = h0; dh[1] = h1;
        dl[0] = l0; dl[1] = l1;
    }

    // ---- convert B tile: W1[n, half*128 + k], n,k in [0,128) ----
    for (int c = tid; c < 128 * 32; c += 256) {
        int n = c >> 5, q = c & 31;
        float4 v = *reinterpret_cast<const float4*>(
            W1 + (size_t)n * NCOLS + half * D + q * 4);
        u32 h0, l0, h1, l1;
        split2(v.x, v.y, h0, l0);
        split2(v.z, v.w, h1, l1);
        u32* dh = reinterpret_cast<u32*>(bHi + n * SA + q * 4);
        u32* dl = reinterpret_cast<u32*>(bLo + n * SA + q * 4);
        dh[0] = h0; dh[1] = h1;
        dl[0] = l0; dl[1] = l1;
    }
    __syncthreads();

    const int wm = (wid & 3) * 32;                // warp M offset
    const int wn = (wid >> 2) * 64;               // warp N offset

    float acc[2][8][4];
    #pragma unroll
    for (int i = 0; i < 2; i++)
        #pragma unroll
        for (int j = 0; j < 8; j++)
            #pragma unroll
            for (int r = 0; r < 4; r++) acc[i][j][r] = 0.f;

    const u32 aHiU = smem_u32(aHi), aLoU = smem_u32(aLo);
    const u32 bHiU = smem_u32(bHi), bLoU = smem_u32(bLo);
    const u32 aBase[3] = { aHiU, aHiU, aLoU };
    const u32 bBase[3] = { bHiU, bLoU, bHiU };

    #pragma unroll
    for (int pass = 0; pass < 3; pass++) {
        const u32 ab = aBase[pass], bb = bBase[pass];
        #pragma unroll
        for (int kb = 0; kb < 8; kb++) {
            u32 a[2][4], b[8][2];
            #pragma unroll
            for (int i = 0; i < 2; i++) {
                u32 addr = ab + (((wm + i * 16 + (lane & 15)) * SA
                                  + kb * 16 + (lane >> 4) * 8) << 1);
                LDMATRIX_X4(a[i][0], a[i][1], a[i][2], a[i][3], addr);
            }
            #pragma unroll
            for (int j = 0; j < 8; j++) {
                u32 addr = bb + (((wn + j * 8 + (lane & 7)) * SA
                                  + kb * 16 + ((lane >> 3) & 1) * 8) << 1);
                LDMATRIX_X2(b[j][0], b[j][1], addr);
            }
            #pragma unroll
            for (int i = 0; i < 2; i++)
                #pragma unroll
                for (int j = 0; j < 8; j++)
                    mma_bf16(acc[i][j], a[i], b[j]);
        }
    }

    // ---- epilogue: fragments -> g_P (fp32) ----
    const int r0 = lane >> 2;
    const int c0 = (lane & 3) * 2;
    #pragma unroll
    for (int i = 0; i < 2; i++) {
        #pragma unroll
        for (int j = 0; j < 8; j++) {
            int col = half * D + wn + j * 8 + c0;
            int mA  = m0 + wm + i * 16 + r0;
            if (mA < nN)
                *reinterpret_cast<float2*>(g_P + (size_t)mA * NCOLS + col) =
                    make_float2(acc[i][j][0], acc[i][j][1]);
            int mB = mA + 8;
            if (mB < nN)
                *reinterpret_cast<float2*>(g_P + (size_t)mB * NCOLS + col) =
                    make_float2(acc[i][j][2], acc[i][j][3]);
        }
    }
}

// ============================================================================
// Kernel 2: per-edge MLP tail. One warp per 2 edges (ILP=2).
//   s = sum_j relu(A[src][j] + B[dst][j] + b1[j]) * w2[j]
//   out[e] = sigmoid(relu(s + b2))
// edge_index dtype sniffed inline (LE int64 < 2^31 => odd words all zero).
// ============================================================================
__global__ __launch_bounds__(256) void edge_kernel(
    const void* __restrict__ edge_index,
    const float* __restrict__ b1,
    const float* __restrict__ W2,
    const float* __restrict__ b2,
    float* __restrict__ out,
    int E)
{
    const int lane   = threadIdx.x & 31;
    const int warp   = (blockIdx.x * blockDim.x + threadIdx.x) >> 5;
    const int nwarps = (gridDim.x * blockDim.x) >> 5;

    const int* ei32 = (const int*)edge_index;
    int det = 0;
    #pragma unroll
    for (int i = 1; i < 16; i += 2) det |= __ldg(&ei32[i]);
    const bool is64 = (det == 0);
    const long long* ei64 = (const long long*)edge_index;

    const float4* __restrict__ P4 = reinterpret_cast<const float4*>(g_P);
    const float4 bias = reinterpret_cast<const float4*>(b1)[lane];
    const float4 w2   = reinterpret_cast<const float4*>(W2)[lane];
    const float  b2v  = *b2;

    for (int e = warp * 2; e < E; e += nwarps * 2) {
        const bool has2 = (e + 1 < E);
        int s0, t0, s1 = 0, t1 = 0;
        if (is64) {
            s0 = (int)ei64[e];     t0 = (int)ei64[E + e];
            if (has2) { s1 = (int)ei64[e + 1]; t1 = (int)ei64[E + e + 1]; }
        } else {
            s0 = ei32[e];          t0 = ei32[E + e];
            if (has2) { s1 = ei32[e + 1]; t1 = ei32[E + e + 1]; }
        }

        float4 a0 = P4[(size_t)s0 * 64 + lane];
        float4 c0 = P4[(size_t)t0 * 64 + 32 + lane];
        float4 a1, c1;
        if (has2) {
            a1 = P4[(size_t)s1 * 64 + lane];
            c1 = P4[(size_t)t1 * 64 + 32 + lane];
        }

        float v0 = fmaxf(a0.x + c0.x + bias.x, 0.f) * w2.x
                 + fmaxf(a0.y + c0.y + bias.y, 0.f) * w2.y
                 + fmaxf(a0.z + c0.z + bias.z, 0.f) * w2.z
                 + fmaxf(a0.w + c0.w + bias.w, 0.f) * w2.w;
        float v1 = 0.f;
        if (has2)
            v1 = fmaxf(a1.x + c1.x + bias.x, 0.f) * w2.x
               + fmaxf(a1.y + c1.y + bias.y, 0.f) * w2.y
               + fmaxf(a1.z + c1.z + bias.z, 0.f) * w2.z
               + fmaxf(a1.w + c1.w + bias.w, 0.f) * w2.w;

        #pragma unroll
        for (int o = 16; o > 0; o >>= 1) {
            v0 += __shfl_xor_sync(0xFFFFFFFFu, v0, o);
            v1 += __shfl_xor_sync(0xFFFFFFFFu, v1, o);
        }

        if (lane == 0) {
            float h0 = fmaxf(v0 + b2v, 0.f);
            out[e] = 1.0f / (1.0f + expf(-h0));
            if (has2) {
                float h1 = fmaxf(v1 + b2v, 0.f);
                out[e + 1] = 1.0f / (1.0f + expf(-h1));
            }
        }
    }
}

// ============================================================================
// Launch
// Inputs: x[f32 N*128], edge_index[2*E i32/i64], W1[f32 128*256], b1[f32 128],
//         W2[f32 128], b2[f32 1]. Output: f32 E.
// ============================================================================
#define GEMM_SMEM (4 * 128 * SA * 2)   // 139264 B

extern "C" void kernel_launch(void* const* d_in, const int* in_sizes, int n_in,
                              void* d_out, int out_size)
{
    const float* x  = (const float*)d_in[0];
    const void*  ei = d_in[1];
    const float* W1 = (const float*)d_in[2];
    const float* b1 = (const float*)d_in[3];
    const float* W2 = (const float*)d_in[4];
    const float* b2 = (const float*)d_in[5];
    float*       out = (float*)d_out;

    const int N = in_sizes[0] / D;   // 100000
    const int E = in_sizes[1] / 2;   // 625000

    cudaFuncSetAttribute(precompute_kernel,
                         cudaFuncAttributeMaxDynamicSharedMemorySize, GEMM_SMEM);

    dim3 g1((N + BM - 1) / BM, 2);
    precompute_kernel<<<g1, 256, GEMM_SMEM>>>(x, W1, N);

    edge_kernel<<<1184, 256>>>(ei, b1, W2, b2, out, E);
}

// round 6
// speedup vs baseline: 1.9618x; 1.7201x over previous
#include <cuda_runtime.h>
#include <cuda_fp16.h>
#include <cuda_bf16.h>
#include <math.h>

#define D         128
#define NCOLS     256
#define MAX_NODES 100000

typedef unsigned int u32;

// P (layer-1 pre-bias activations, split A|B) stored as fp16
__device__ __half g_Ph[(size_t)MAX_NODES * NCOLS];
// W1 pre-converted to split-bf16, laid out in mma.sync B-fragment order:
// index = ((jt*8 + kb)*32 + lane)*2 + {0,1}  (jt: n-tile 0..31, kb: k-chunk 0..7)
__device__ u32 g_Whi[32 * 8 * 32 * 2];
__device__ u32 g_Wlo[32 * 8 * 32 * 2];

// ============================================================================
// helpers
// ============================================================================
__device__ __forceinline__ void mma_bf16(float* d, const u32* a, const u32* b) {
    asm volatile(
        "mma.sync.aligned.m16n8k16.row.col.f32.bf16.bf16.f32 "
        "{%0, %1, %2, %3}, {%4, %5, %6, %7}, {%8, %9}, {%0, %1, %2, %3};"
        : "+f"(d[0]), "+f"(d[1]), "+f"(d[2]), "+f"(d[3])
        : "r"(a[0]), "r"(a[1]), "r"(a[2]), "r"(a[3]), "r"(b[0]), "r"(b[1]));
}

// split fp32 pair -> bf16x2 hi word (rn) + bf16x2 residual word.
// low half of each b32 = first element (matches fragment memory order).
__device__ __forceinline__ void split2(float f0, float f1, u32& h, u32& l) {
    __nv_bfloat162 hv = __floats2bfloat162_rn(f0, f1);   // .x=f0(lo), .y=f1(hi)
    u32 hu = *reinterpret_cast<u32*>(&hv);
    float h0 = __uint_as_float(hu << 16);
    float h1 = __uint_as_float(hu & 0xFFFF0000u);
    __nv_bfloat162 lv = __floats2bfloat162_rn(f0 - h0, f1 - h1);
    h = hu;
    l = *reinterpret_cast<u32*>(&lv);
}

// ============================================================================
// Kernel 0: convert W1 into split-bf16 B-fragments (runs once, 8192 threads).
//   Bmat[n, k] = W1[n, k]           (n < 128)   -> P cols 0..127   (A half)
//              = W1[n-128, 128+k]   (n >= 128)  -> P cols 128..255 (B half)
// Fragment (jt, kb, lane): n = jt*8 + lane/4, k0 = kb*16 + (lane%4)*2
//   word0 = (Bmat[n,k0], Bmat[n,k0+1]); word1 = (Bmat[n,k0+8], Bmat[n,k0+9])
// ============================================================================
__global__ void prep_w_kernel(const float* __restrict__ W1)
{
    const int jt   = blockIdx.x;          // 0..31
    const int kb   = threadIdx.x >> 5;    // 0..7
    const int lane = threadIdx.x & 31;
    const int n    = jt * 8 + (lane >> 2);
    const int k0   = kb * 16 + (lane & 3) * 2;

    const float* row = (n < 128)
        ? (W1 + (size_t)n * NCOLS)
        : (W1 + (size_t)(n - 128) * NCOLS + 128);

    float f0 = row[k0],     f1 = row[k0 + 1];
    float f2 = row[k0 + 8], f3 = row[k0 + 9];

    u32 h0, l0, h1, l1;
    split2(f0, f1, h0, l0);
    split2(f2, f3, h1, l1);

    size_t idx = (((size_t)(jt * 8 + kb)) * 32 + lane) * 2;
    g_Whi[idx] = h0;  g_Whi[idx + 1] = h1;
    g_Wlo[idx] = l0;  g_Wlo[idx + 1] = l1;
}

// ============================================================================
// Kernel 1: P = x @ Bmat^T, split-bf16 mma.sync (3 chains), no smem.
// grid = ceil(N/128), block = 512 (16 warps: 4 M-warps x 4 N-warps, 32x64).
// A-fragments loaded as fp32 float2 from x and split in registers.
// ============================================================================
__global__ __launch_bounds__(512, 1) void precompute_kernel(
    const float* __restrict__ x,
    int nN)
{
    const int tid  = threadIdx.x;
    const int wid  = tid >> 5;
    const int lane = tid & 31;
    const int wm   = (wid & 3) * 32;      // M offset within CTA tile
    const int wjt  = (wid >> 2) * 8;      // first n-tile of this warp
    const int r    = lane >> 2;
    const int c2   = (lane & 3) * 2;
    const int m0   = blockIdx.x * 128;

    float acc[2][8][4];
    #pragma unroll
    for (int i = 0; i < 2; i++)
        #pragma unroll
        for (int j = 0; j < 8; j++)
            #pragma unroll
            for (int q = 0; q < 4; q++) acc[i][j][q] = 0.f;

    #pragma unroll 2
    for (int kb = 0; kb < 8; kb++) {
        const int kk = kb * 16 + c2;

        // ---- A fragments: load fp32, split in registers ----
        u32 ahi[2][4], alo[2][4];
        #pragma unroll
        for (int i = 0; i < 2; i++) {
            const int mA = m0 + wm + i * 16 + r;
            const int mB = mA + 8;
            const float* pA = x + (size_t)mA * D + kk;
            const float* pB = x + (size_t)mB * D + kk;
            float2 z = make_float2(0.f, 0.f);
            float2 v00 = (mA < nN) ? *reinterpret_cast<const float2*>(pA)     : z;
            float2 v02 = (mA < nN) ? *reinterpret_cast<const float2*>(pA + 8) : z;
            float2 v10 = (mB < nN) ? *reinterpret_cast<const float2*>(pB)     : z;
            float2 v12 = (mB < nN) ? *reinterpret_cast<const float2*>(pB + 8) : z;
            split2(v00.x, v00.y, ahi[i][0], alo[i][0]);
            split2(v10.x, v10.y, ahi[i][1], alo[i][1]);
            split2(v02.x, v02.y, ahi[i][2], alo[i][2]);
            split2(v12.x, v12.y, ahi[i][3], alo[i][3]);
        }

        // ---- B_hi: passes x_hi*W_hi and x_lo*W_hi ----
        #pragma unroll
        for (int j = 0; j < 8; j++) {
            size_t bidx = (((size_t)(wjt + j) * 8 + kb) * 32 + lane) * 2;
            uint2 bh = *reinterpret_cast<const uint2*>(&g_Whi[bidx]);
            u32 bf[2] = { bh.x, bh.y };
            mma_bf16(acc[0][j], ahi[0], bf);
            mma_bf16(acc[1][j], ahi[1], bf);
            mma_bf16(acc[0][j], alo[0], bf);
            mma_bf16(acc[1][j], alo[1], bf);
        }
        // ---- B_lo: pass x_hi*W_lo ----
        #pragma unroll
        for (int j = 0; j < 8; j++) {
            size_t bidx = (((size_t)(wjt + j) * 8 + kb) * 32 + lane) * 2;
            uint2 bl = *reinterpret_cast<const uint2*>(&g_Wlo[bidx]);
            u32 bf[2] = { bl.x, bl.y };
            mma_bf16(acc[0][j], ahi[0], bf);
            mma_bf16(acc[1][j], ahi[1], bf);
        }
    }

    // ---- epilogue: fragments -> g_Ph (fp16) ----
    #pragma unroll
    for (int i = 0; i < 2; i++) {
        #pragma unroll
        for (int j = 0; j < 8; j++) {
            const int col = (wjt + j) * 8 + c2;
            const int mA  = m0 + wm + i * 16 + r;
            if (mA < nN) {
                __half2 hv = __floats2half2_rn(acc[i][j][0], acc[i][j][1]);
                *reinterpret_cast<u32*>(&g_Ph[(size_t)mA * NCOLS + col]) =
                    *reinterpret_cast<u32*>(&hv);
            }
            const int mB = mA + 8;
            if (mB < nN) {
                __half2 hv = __floats2half2_rn(acc[i][j][2], acc[i][j][3]);
                *reinterpret_cast<u32*>(&g_Ph[(size_t)mB * NCOLS + col]) =
                    *reinterpret_cast<u32*>(&hv);
            }
        }
    }
}

// ============================================================================
// Kernel 2: per-edge MLP tail (fp16 P). One warp per 2 edges.
//   s = sum_j relu(A[src][j] + B[dst][j] + b1[j]) * w2[j]
//   out[e] = sigmoid(relu(s + b2))
// Lane j covers features 4j..4j+3 (uint2 = 4 halves per matrix per lane).
// ============================================================================
__global__ __launch_bounds__(256) void edge_kernel(
    const void* __restrict__ edge_index,
    const float* __restrict__ b1,
    const float* __restrict__ W2,
    const float* __restrict__ b2,
    float* __restrict__ out,
    int E)
{
    const int lane   = threadIdx.x & 31;
    const int warp   = (blockIdx.x * blockDim.x + threadIdx.x) >> 5;
    const int nwarps = (gridDim.x * blockDim.x) >> 5;

    // dtype sniff: LE int64 (<2^31) => all odd 32-bit words zero
    const int* ei32 = (const int*)edge_index;
    int det = 0;
    #pragma unroll
    for (int i = 1; i < 16; i += 2) det |= __ldg(&ei32[i]);
    const bool is64 = (det == 0);
    const long long* ei64 = (const long long*)edge_index;

    const uint2* __restrict__ P2 = reinterpret_cast<const uint2*>(g_Ph);
    const float4 bias = reinterpret_cast<const float4*>(b1)[lane];
    const float4 w2   = reinterpret_cast<const float4*>(W2)[lane];
    const float  b2v  = *b2;

    for (int e = warp * 2; e < E; e += nwarps * 2) {
        const bool has2 = (e + 1 < E);
        int s0, t0, s1 = 0, t1 = 0;
        if (is64) {
            s0 = (int)ei64[e];     t0 = (int)ei64[E + e];
            if (has2) { s1 = (int)ei64[e + 1]; t1 = (int)ei64[E + e + 1]; }
        } else {
            s0 = ei32[e];          t0 = ei32[E + e];
            if (has2) { s1 = ei32[e + 1]; t1 = ei32[E + e + 1]; }
        }

        uint2 ua0 = P2[(size_t)s0 * 64 + lane];
        uint2 uc0 = P2[(size_t)t0 * 64 + 32 + lane];
        uint2 ua1, uc1;
        if (has2) {
            ua1 = P2[(size_t)s1 * 64 + lane];
            uc1 = P2[(size_t)t1 * 64 + 32 + lane];
        }

        float2 a0l = __half22float2(*reinterpret_cast<__half2*>(&ua0.x));
        float2 a0h = __half22float2(*reinterpret_cast<__half2*>(&ua0.y));
        float2 c0l = __half22float2(*reinterpret_cast<__half2*>(&uc0.x));
        float2 c0h = __half22float2(*reinterpret_cast<__half2*>(&uc0.y));

        float v0 = fmaxf(a0l.x + c0l.x + bias.x, 0.f) * w2.x
                 + fmaxf(a0l.y + c0l.y + bias.y, 0.f) * w2.y
                 + fmaxf(a0h.x + c0h.x + bias.z, 0.f) * w2.z
                 + fmaxf(a0h.y + c0h.y + bias.w, 0.f) * w2.w;

        float v1 = 0.f;
        if (has2) {
            float2 a1l = __half22float2(*reinterpret_cast<__half2*>(&ua1.x));
            float2 a1h = __half22float2(*reinterpret_cast<__half2*>(&ua1.y));
            float2 c1l = __half22float2(*reinterpret_cast<__half2*>(&uc1.x));
            float2 c1h = __half22float2(*reinterpret_cast<__half2*>(&uc1.y));
            v1 = fmaxf(a1l.x + c1l.x + bias.x, 0.f) * w2.x
               + fmaxf(a1l.y + c1l.y + bias.y, 0.f) * w2.y
               + fmaxf(a1h.x + c1h.x + bias.z, 0.f) * w2.z
               + fmaxf(a1h.y + c1h.y + bias.w, 0.f) * w2.w;
        }

        #pragma unroll
        for (int o = 16; o > 0; o >>= 1) {
            v0 += __shfl_xor_sync(0xFFFFFFFFu, v0, o);
            v1 += __shfl_xor_sync(0xFFFFFFFFu, v1, o);
        }

        if (lane == 0) {
            float h0 = fmaxf(v0 + b2v, 0.f);
            out[e] = 1.0f / (1.0f + expf(-h0));
            if (has2) {
                float h1 = fmaxf(v1 + b2v, 0.f);
                out[e + 1] = 1.0f / (1.0f + expf(-h1));
            }
        }
    }
}

// ============================================================================
// Launch
// Inputs: x[f32 N*128], edge_index[2*E i32/i64], W1[f32 128*256], b1[f32 128],
//         W2[f32 128], b2[f32 1]. Output: f32 E.
// ============================================================================
extern "C" void kernel_launch(void* const* d_in, const int* in_sizes, int n_in,
                              void* d_out, int out_size)
{
    const float* x  = (const float*)d_in[0];
    const void*  ei = d_in[1];
    const float* W1 = (const float*)d_in[2];
    const float* b1 = (const float*)d_in[3];
    const float* W2 = (const float*)d_in[4];
    const float* b2 = (const float*)d_in[5];
    float*       out = (float*)d_out;

    const int N = in_sizes[0] / D;   // 100000
    const int E = in_sizes[1] / 2;   // 625000

    prep_w_kernel<<<32, 256>>>(W1);
    precompute_kernel<<<(N + 127) / 128, 512>>>(x, N);
    edge_kernel<<<1184, 256>>>(ei, b1, W2, b2, out, E);
}